// round 4
// baseline (speedup 1.0000x reference)
#include <cuda_runtime.h>
#include <cstdint>

// Problem constants
#define BSZ    256
#define HID    1024
#define TSTEPS 64
#define N4     4096
#define OUTW   64
#define INLEN  512
#define K8     128                 // k8-chunks in K=1024

// GEMM tiling
#define BM 128
#define BN 64
#define NKT 32                     // k-iters (BK=32)
#define STAGE_F 6144               // 4096 A + 2048 B floats per stage
#define NSLOT 3
#define SMEM_BYTES (NSLOT * STAGE_F * 4)   // 73728
#define CSTRIDE 68
#define A_MT_STRIDE (K8 * 8 * 32 * 4)      // 131072 floats per 128-row m-tile
#define W_NT_STRIDE (K8 * 8 * 32 * 2)      // 65536 floats per 64-col n-tile
#define NBLK 128

// h0 split
#define H0S 8
#define H0ROWS (INLEN / H0S)       // 64

// ---------------- device scratch ----------------
__device__ float  g_Whp[N4 * HID];
__device__ float  g_Wcp[N4 * HID];
__device__ float  g_WoutP[OUTW * HID];
__device__ float  g_g0[N4];
__device__ float  g_bp[N4];
__device__ float  g_act0[BSZ * HID];
__device__ float  g_act1[BSZ * HID];
__device__ float  g_c[BSZ * HID];
__device__ float  g_out[BSZ * TSTEPS * HID];
__device__ float  g_A2[BSZ * TSTEPS * HID];
__device__ float4 g_part4[H0S * BSZ * (HID / 4)];
__device__ unsigned g_bar_count = 0;
__device__ unsigned g_bar_gen   = 0;

// ---------------- helpers ----------------
__device__ __forceinline__ float tf32r(float x) {
    uint32_t u;
    asm("cvt.rna.tf32.f32 %0, %1;" : "=r"(u) : "f"(x));
    return __uint_as_float(u);
}
__device__ __forceinline__ float sigm(float x) { return 1.0f / (1.0f + __expf(-x)); }
__device__ __forceinline__ float tanh_acc(float x) { return 2.0f / (1.0f + __expf(-2.0f * x)) - 1.0f; }

// A-side permuted index: [mt][kc][mb8][lane32][4]
__device__ __forceinline__ size_t aperm_idx(int r, int k) {
    int mt = r >> 7, rr = r & 127;
    int mb = rr >> 4, rl = rr & 15;
    int half  = rl >> 3;
    int lane  = ((rl & 7) << 2) | (k & 3);
    int kc    = k >> 3;
    int khalf = (k >> 2) & 1;
    return ((((size_t)mt * K8 + kc) * 8 + mb) * 32 + lane) * 4 + khalf * 2 + half;
}

__device__ __forceinline__ void cp16(float* dst_smem, const float* src) {
    uint32_t d = (uint32_t)__cvta_generic_to_shared(dst_smem);
    asm volatile("cp.async.cg.shared.global [%0], [%1], 16;\n" :: "r"(d), "l"(src));
}
__device__ __forceinline__ void mma_tf32(float* c, const float4& a, float bx, float by) {
    asm volatile(
        "mma.sync.aligned.m16n8k8.row.col.f32.tf32.tf32.f32 "
        "{%0,%1,%2,%3}, {%4,%5,%6,%7}, {%8,%9}, {%0,%1,%2,%3};\n"
        : "+f"(c[0]), "+f"(c[1]), "+f"(c[2]), "+f"(c[3])
        : "r"(__float_as_uint(a.x)), "r"(__float_as_uint(a.y)),
          "r"(__float_as_uint(a.z)), "r"(__float_as_uint(a.w)),
          "r"(__float_as_uint(bx)), "r"(__float_as_uint(by)));
}

// grid barrier (release/acquire)
__device__ __forceinline__ void grid_bar() {
    __syncthreads();
    if (threadIdx.x == 0) {
        unsigned gen;
        asm volatile("ld.acquire.gpu.u32 %0, [%1];" : "=r"(gen) : "l"(&g_bar_gen) : "memory");
        unsigned old;
        asm volatile("atom.release.gpu.add.u32 %0, [%1], %2;"
                     : "=r"(old) : "l"(&g_bar_count), "r"(1u) : "memory");
        if (old == NBLK - 1) {
            asm volatile("st.relaxed.gpu.u32 [%0], %1;" :: "l"(&g_bar_count), "r"(0u) : "memory");
            asm volatile("st.release.gpu.u32 [%0], %1;" :: "l"(&g_bar_gen), "r"(gen + 1u) : "memory");
        } else {
            unsigned cur;
            do {
                asm volatile("ld.acquire.gpu.u32 %0, [%1];" : "=r"(cur) : "l"(&g_bar_gen) : "memory");
            } while (cur == gen);
        }
    }
    __syncthreads();
}

// ---------------- prep: permuted weights ----------------
// B layout: [nt][kc2 64][nb 8][lane 32] float4 = {kE,kE+4,kO,kO+4}; kc2 = k8-pair
__global__ void prep_weights(const float* __restrict__ w_ih, const float* __restrict__ w_hh) {
    int gid  = blockIdx.x * 256 + threadIdx.x;   // 64*64*8*32 = 1,048,576 float4 positions
    int lane = gid & 31;
    int nb   = (gid >> 5) & 7;
    int nt   = gid >> 14;
    int np   = nt * 64 + nb * 8 + (lane >> 2);
    int h = np >> 2, g = np & 3;
    int j = (g << 10) + h;
    int kc2 = (gid >> 8) & 63;
    int kA  = kc2 * 16 + (lane & 3);
    const float* rih = w_ih + (size_t)j * HID;
    const float* rhh = w_hh + (size_t)j * HID;
    float h0 = rhh[kA],     h1 = rhh[kA + 4], h2 = rhh[kA + 8], h3 = rhh[kA + 12];
    float c0 = rih[kA] + h0, c1 = rih[kA + 4] + h1, c2 = rih[kA + 8] + h2, c3 = rih[kA + 12] + h3;
    reinterpret_cast<float4*>(g_Whp)[gid] =
        make_float4(tf32r(h0), tf32r(h1), tf32r(h2), tf32r(h3));
    reinterpret_cast<float4*>(g_Wcp)[gid] =
        make_float4(tf32r(c0), tf32r(c1), tf32r(c2), tf32r(c3));
}

__global__ void prep_wout(const float* __restrict__ w_out) {
    int gid  = blockIdx.x * 256 + threadIdx.x;   // 64*8*32 = 16384 float4 positions
    int lane = gid & 31;
    int nb   = (gid >> 5) & 7;
    int kc2  = (gid >> 8) & 63;
    int j    = nb * 8 + (lane >> 2);
    int kA   = kc2 * 16 + (lane & 3);
    const float* r = w_out + (size_t)j * HID;
    reinterpret_cast<float4*>(g_WoutP)[gid] =
        make_float4(tf32r(r[kA]), tf32r(r[kA + 4]), tf32r(r[kA + 8]), tf32r(r[kA + 12]));
}

__global__ void prep_bias(const float* __restrict__ st, const float* __restrict__ w_ih,
                          const float* __restrict__ b_ih, const float* __restrict__ b_hh) {
    int gw   = (blockIdx.x * blockDim.x + threadIdx.x) >> 5;
    int lane = threadIdx.x & 31;
    for (int np = gw; np < N4; np += 1024) {
        int h = np >> 2, g = np & 3;
        int j = (g << 10) + h;
        const float* wr = w_ih + (size_t)j * HID;
        float s = 0.f;
        #pragma unroll 8
        for (int k = lane; k < HID; k += 32) s += st[k] * wr[k];
        #pragma unroll
        for (int off = 16; off > 0; off >>= 1) s += __shfl_xor_sync(0xffffffffu, s, off);
        if (lane == 0) {
            float bs = b_ih[j] + b_hh[j];
            g_bp[np] = bs;
            g_g0[np] = s + bs;
        }
    }
}

// ---------------- h0 ----------------
__global__ void h0_part(const float* __restrict__ qf, const float* __restrict__ w_in) {
    __shared__ float sw[H0ROWS];
    int b = blockIdx.x, s = blockIdx.y, tid = threadIdx.x;
    if (tid < H0ROWS) sw[tid] = w_in[s * H0ROWS + tid];
    __syncthreads();
    const float4* q = reinterpret_cast<const float4*>(qf)
                    + ((size_t)b * INLEN + s * H0ROWS) * (HID / 4) + tid;
    float4 acc = make_float4(0.f, 0.f, 0.f, 0.f);
    #pragma unroll 16
    for (int i = 0; i < H0ROWS; i++) {
        float4 v = q[(size_t)i * (HID / 4)];
        float w = sw[i];
        acc.x = fmaf(v.x, w, acc.x);
        acc.y = fmaf(v.y, w, acc.y);
        acc.z = fmaf(v.z, w, acc.z);
        acc.w = fmaf(v.w, w, acc.w);
    }
    g_part4[((size_t)s * BSZ + b) * (HID / 4) + tid] = acc;
}

__global__ void h0_comb(const float* __restrict__ b_in) {
    int b = blockIdx.x, tid = threadIdx.x;
    float4 a = make_float4(0.f, 0.f, 0.f, 0.f);
    #pragma unroll
    for (int s = 0; s < H0S; s++) {
        float4 p = g_part4[((size_t)s * BSZ + b) * (HID / 4) + tid];
        a.x += p.x; a.y += p.y; a.z += p.z; a.w += p.w;
    }
    float bb = b_in[0];
    int k = tid * 4;
    g_act0[aperm_idx(b, k + 0)] = tf32r(a.x + bb);
    g_act0[aperm_idx(b, k + 1)] = tf32r(a.y + bb);
    g_act0[aperm_idx(b, k + 2)] = tf32r(a.z + bb);
    g_act0[aperm_idx(b, k + 3)] = tf32r(a.w + bb);
    reinterpret_cast<float4*>(g_c)[(size_t)b * (HID / 4) + tid] =
        make_float4(0.f, 0.f, 0.f, 0.f);
}

// ---------------- GEMM core ----------------
__device__ __forceinline__ void stage_cp(float* smem_p, const float* Ablk,
                                         const float* Wblk, int kt, int slot, int tid) {
    float* s = smem_p + slot * STAGE_F;
    const float* gA = Ablk + (size_t)kt * 4096;
    const float* gB = Wblk + (size_t)kt * 2048;
    #pragma unroll
    for (int i = 0; i < 4; i++) { int c = tid + i * 256; cp16(s + c * 4, gA + c * 4); }
    #pragma unroll
    for (int i = 0; i < 2; i++) { int c = tid + i * 256; cp16(s + 4096 + c * 4, gB + c * 4); }
}

__device__ __forceinline__ void run_gemm(const float* Ablk, const float* Wblk,
                                         float (&acc)[2][4][4],
                                         int tid, int lane, int wm, int wn) {
    extern __shared__ float smem[];
    #pragma unroll
    for (int i = 0; i < 2; i++)
        #pragma unroll
        for (int j = 0; j < 4; j++)
            #pragma unroll
            for (int r = 0; r < 4; r++) acc[i][j][r] = 0.f;

    stage_cp(smem, Ablk, Wblk, 0, 0, tid);
    asm volatile("cp.async.commit_group;\n" ::: "memory");
    stage_cp(smem, Ablk, Wblk, 1, 1, tid);
    asm volatile("cp.async.commit_group;\n" ::: "memory");

    int slotC = 0, slotS = 2;
    #pragma unroll 1
    for (int kt = 0; kt < NKT; kt++) {
        if (kt == NKT - 1) asm volatile("cp.async.wait_group 0;\n" ::: "memory");
        else               asm volatile("cp.async.wait_group 1;\n" ::: "memory");
        __syncthreads();
        if (kt + 2 < NKT) {
            stage_cp(smem, Ablk, Wblk, kt + 2, slotS, tid);
            asm volatile("cp.async.commit_group;\n" ::: "memory");
        }
        const float4* A4 = reinterpret_cast<const float4*>(smem + slotC * STAGE_F);
        const float4* B4 = reinterpret_cast<const float4*>(smem + slotC * STAGE_F + 4096);

        float4 af[2][2], bq[2][4];
        #pragma unroll
        for (int mb = 0; mb < 2; mb++) af[0][mb] = A4[(wm * 2 + mb) * 32 + lane];
        #pragma unroll
        for (int nb = 0; nb < 4; nb++) bq[0][nb] = B4[(wn * 4 + nb) * 32 + lane];

        #pragma unroll
        for (int kc = 0; kc < 4; kc++) {
            if (kc < 3) {
                #pragma unroll
                for (int mb = 0; mb < 2; mb++)
                    af[(kc + 1) & 1][mb] = A4[((kc + 1) * 8 + wm * 2 + mb) * 32 + lane];
            }
            if (kc == 0) {
                #pragma unroll
                for (int nb = 0; nb < 4; nb++)
                    bq[1][nb] = B4[(8 + wn * 4 + nb) * 32 + lane];
            }
            #pragma unroll
            for (int mb = 0; mb < 2; mb++)
                #pragma unroll
                for (int nb = 0; nb < 4; nb++) {
                    const float4& b4 = bq[kc >> 1][nb];
                    if (kc & 1) mma_tf32(acc[mb][nb], af[kc & 1][mb], b4.z, b4.w);
                    else        mma_tf32(acc[mb][nb], af[kc & 1][mb], b4.x, b4.y);
                }
        }
        slotC++; if (slotC == NSLOT) slotC = 0;
        slotS++; if (slotS == NSLOT) slotS = 0;
    }
    __syncthreads();   // slots free before C stash
}

__device__ __forceinline__ void store_C(float (&acc)[2][4][4], int lane, int wm, int wn) {
    extern __shared__ float smem[];
    float* Cs = smem;
    #pragma unroll
    for (int mb = 0; mb < 2; mb++)
        #pragma unroll
        for (int nb = 0; nb < 4; nb++) {
            int r  = (wm * 2 + mb) * 16 + (lane >> 2);
            int cc = (wn * 4 + nb) * 8 + (lane & 3) * 2;
            Cs[r * CSTRIDE + cc]           = acc[mb][nb][0];
            Cs[r * CSTRIDE + cc + 1]       = acc[mb][nb][1];
            Cs[(r + 8) * CSTRIDE + cc]     = acc[mb][nb][2];
            Cs[(r + 8) * CSTRIDE + cc + 1] = acc[mb][nb][3];
        }
}

// ---------------- persistent LSTM + projection ----------------
__global__ void __launch_bounds__(256, 1)
lstm_persist(const float* __restrict__ b_out, float* __restrict__ probs_dst) {
    extern __shared__ float smem[];
    const int tid  = threadIdx.x;
    const int lane = tid & 31;
    const int w    = tid >> 5;
    const int wm   = w & 3;
    const int wn   = w >> 2;
    const int mt   = blockIdx.x;       // 0..1
    const int nt   = blockIdx.y;       // 0..63
    const int mBase = mt * BM;
    const int nBase = nt * BN;

    float acc[2][4][4];

    #pragma unroll 1
    for (int t = 0; t < TSTEPS; t++) {
        const float* A    = (t & 1) ? g_act1 : g_act0;
        float*       aout = (t & 1) ? g_act0 : g_act1;
        const float* W    = (t == 0) ? g_Whp : g_Wcp;
        const float* bias = (t == 0) ? g_g0  : g_bp;

        run_gemm(A + (size_t)mt * A_MT_STRIDE, W + (size_t)nt * W_NT_STRIDE,
                 acc, tid, lane, wm, wn);
        store_C(acc, lane, wm, wn);
        __syncthreads();

        const float* Cs = smem;
        for (int idx = tid; idx < BM * (BN / 4); idx += 256) {
            int row = idx >> 4, hh = idx & 15;
            int b  = mBase + row;
            int hg = (nBase >> 2) + hh;
            float4 gv = *reinterpret_cast<const float4*>(&Cs[row * CSTRIDE + hh * 4]);
            float4 bb = *reinterpret_cast<const float4*>(&bias[nBase + hh * 4]);
            float gi = gv.x + bb.x;
            float gf = gv.y + bb.y;
            float gg = gv.z + bb.z;
            float go = gv.w + bb.w;
            float cOld = g_c[(size_t)b * HID + hg];
            float cN = sigm(gf) * cOld + sigm(gi) * tanh_acc(gg);
            float hN = sigm(go) * tanh_acc(cN);
            g_c[(size_t)b * HID + hg] = cN;
            g_out[((size_t)b * TSTEPS + t) * HID + hg] = hN;
            float hr = tf32r(hN);
            aout[aperm_idx(b, hg)] = hr;
            g_A2[aperm_idx(b * TSTEPS + t, hg)] = hr;
        }
        grid_bar();
    }

    // projection: M=16384 rows, 128 blocks x 128-row tiles, N=64
    if (probs_dst != nullptr) {
        int bid = blockIdx.x + 2 * blockIdx.y;     // 0..127
        run_gemm(g_A2 + (size_t)bid * A_MT_STRIDE, g_WoutP, acc, tid, lane, wm, wn);
        store_C(acc, lane, wm, wn);
        __syncthreads();
        const float* Cs = smem;
        int pBase = bid * BM;
        for (int idx = tid; idx < BM * OUTW; idx += 256) {
            int row = idx >> 6, col = idx & 63;
            probs_dst[(size_t)(pBase + row) * OUTW + col] = Cs[row * CSTRIDE + col] + b_out[col];
        }
    }
}

// ---------------- host ----------------
extern "C" void kernel_launch(void* const* d_in, const int* in_sizes, int n_in,
                              void* d_out, int out_size) {
    const float* qf    = (const float*)d_in[1];
    const float* st    = (const float*)d_in[4];
    const float* w_in  = (const float*)d_in[5];
    const float* b_in  = (const float*)d_in[6];
    const float* w_ih  = (const float*)d_in[7];
    const float* w_hh  = (const float*)d_in[8];
    const float* b_ih  = (const float*)d_in[9];
    const float* b_hh  = (const float*)d_in[10];
    const float* w_out = (const float*)d_in[11];
    const float* b_out = (const float*)d_in[12];
    float* out = (float*)d_out;

    float* p_hout;
    cudaGetSymbolAddress((void**)&p_hout, g_out);

    cudaFuncSetAttribute(lstm_persist, cudaFuncAttributeMaxDynamicSharedMemorySize, SMEM_BYTES);

    prep_weights<<<(64 * 64 * 8 * 32) / 256, 256>>>(w_ih, w_hh);
    prep_wout<<<(64 * 8 * 32) / 256, 256>>>(w_out);
    prep_bias<<<128, 256>>>(st, w_ih, b_ih, b_hh);
    h0_part<<<dim3(BSZ, H0S), 256>>>(qf, w_in);
    h0_comb<<<BSZ, 256>>>(b_in);

    // output routing: reference returns (probs, output)
    const long long PROBS_N = (long long)BSZ * TSTEPS * OUTW;
    const long long OUT_N   = (long long)BSZ * TSTEPS * HID;
    float* probs_dst = nullptr;
    bool copy_hidden = false;
    long long hidden_off = 0;
    if ((long long)out_size >= PROBS_N + OUT_N) {
        probs_dst = out;
        copy_hidden = true;
        hidden_off = PROBS_N;
    } else if ((long long)out_size == OUT_N) {
        copy_hidden = true;
    } else {
        probs_dst = out;
    }

    lstm_persist<<<dim3(2, 64), 256, SMEM_BYTES>>>(b_out, probs_dst);

    if (copy_hidden) {
        cudaMemcpyAsync(out + hidden_off, p_hout, OUT_N * sizeof(float),
                        cudaMemcpyDeviceToDevice);
    }
}

// round 6
// speedup vs baseline: 1.5174x; 1.5174x over previous
#include <cuda_runtime.h>
#include <cuda_fp16.h>
#include <cstdint>

// Problem constants
#define BSZ    256
#define HID    1024
#define TSTEPS 64
#define N4     4096
#define OUTW   64
#define INLEN  512

// GEMM tiling: per CTA M=128, N=64, K staged in BK=64 chunks (fp16 operands)
#define BM 128
#define BN 64
#define NKT 16                       // 1024 / 64
#define SLOT_BYTES 24576             // A 16KB + B 8KB
#define NSLOTS 4
#define SMEM_BYTES (NSLOTS * SLOT_BYTES)   // 98304
#define CSTRIDE 68
#define NBLK 128
#define A_MT_ELEMS 131072            // 128 rows * 1024 k (fp16) per m-tile
#define B_NT_ELEMS 65536             // 64 rows * 1024 k (fp16) per n-tile

// h0 split
#define H0S 8
#define H0ROWS (INLEN / H0S)

// ---------------- device scratch ----------------
__device__ __half g_Whp[N4 * HID];          // fragment-permuted w_hh          (step 0)
__device__ __half g_Wcp[N4 * HID];          // fragment-permuted w_ih + w_hh   (steps >=1)
__device__ __half g_WoutP[OUTW * HID];      // fragment-permuted w_out
__device__ float  g_g0[N4];
__device__ float  g_bp[N4];
__device__ __half g_act0[BSZ * HID];        // fragment-permuted activations (ping)
__device__ __half g_act1[BSZ * HID];        // (pong)
__device__ __half g_A2[BSZ * TSTEPS * HID]; // hiddens, fragment-permuted (projection A)
__device__ float  g_out[BSZ * TSTEPS * HID];
__device__ float4 g_part4[H0S * BSZ * (HID / 4)];
__device__ unsigned g_bar_count = 0;
__device__ unsigned g_bar_gen   = 0;

// ---------------- helpers ----------------
__device__ __forceinline__ float sigm(float x) { return 1.0f / (1.0f + __expf(-x)); }
__device__ __forceinline__ float tanh_acc(float x) { return 2.0f / (1.0f + __expf(-2.0f * x)) - 1.0f; }

// A-side fragment-permuted index for mma.m16n8k16 A frags:
//   [mt][kc16(64)][mb(8)][lane(32)][8 halves]  — one LDS.128 per 16x16 block per lane
__device__ __forceinline__ size_t a_idx(int mt, int r, int k) {
    int kc = k >> 4, kk = k & 15;
    int mb = r >> 4, rl = r & 15;
    int lane = ((rl & 7) << 2) | ((kk >> 1) & 3);
    int idx8 = ((kk >> 3) << 2) | ((rl >> 3) << 1) | (kk & 1);
    return ((((size_t)mt * 64 + kc) * 8 + mb) * 32 + lane) * 8 + idx8;
}
// B-side: [nt][kc32(32)][nb(8)][lane(32)][8 halves] — one LDS.128 = B frags for 2 k-steps
__device__ __forceinline__ size_t b_idx(int nt, int nrow, int k) {
    int kc32 = k >> 5, sub = (k >> 4) & 1, kk = k & 15;
    int nb = nrow >> 3, c = nrow & 7;
    int lane = (c << 2) | ((kk >> 1) & 3);
    int idx8 = (sub << 2) | (((kk >> 3) & 1) << 1) | (kk & 1);
    return ((((size_t)nt * 32 + kc32) * 8 + nb) * 32 + lane) * 8 + idx8;
}

__device__ __forceinline__ void cp16c(char* dst, const char* src) {
    uint32_t d = (uint32_t)__cvta_generic_to_shared(dst);
    asm volatile("cp.async.cg.shared.global [%0], [%1], 16;\n" :: "r"(d), "l"(src));
}
__device__ __forceinline__ void mma_f16(float* c, const float4& a, float bx, float by) {
    asm volatile(
        "mma.sync.aligned.m16n8k16.row.col.f32.f16.f16.f32 "
        "{%0,%1,%2,%3}, {%4,%5,%6,%7}, {%8,%9}, {%0,%1,%2,%3};\n"
        : "+f"(c[0]), "+f"(c[1]), "+f"(c[2]), "+f"(c[3])
        : "r"(__float_as_uint(a.x)), "r"(__float_as_uint(a.y)),
          "r"(__float_as_uint(a.z)), "r"(__float_as_uint(a.w)),
          "r"(__float_as_uint(bx)), "r"(__float_as_uint(by)));
}

__device__ __forceinline__ void grid_bar() {
    __syncthreads();
    if (threadIdx.x == 0) {
        unsigned gen;
        asm volatile("ld.acquire.gpu.u32 %0, [%1];" : "=r"(gen) : "l"(&g_bar_gen) : "memory");
        unsigned old;
        asm volatile("atom.release.gpu.add.u32 %0, [%1], %2;"
                     : "=r"(old) : "l"(&g_bar_count), "r"(1u) : "memory");
        if (old == NBLK - 1) {
            asm volatile("st.relaxed.gpu.u32 [%0], %1;" :: "l"(&g_bar_count), "r"(0u) : "memory");
            asm volatile("st.release.gpu.u32 [%0], %1;" :: "l"(&g_bar_gen), "r"(gen + 1u) : "memory");
        } else {
            unsigned cur;
            do {
                asm volatile("ld.acquire.gpu.u32 %0, [%1];" : "=r"(cur) : "l"(&g_bar_gen) : "memory");
            } while (cur == gen);
        }
    }
    __syncthreads();
}

// ---------------- prep kernels ----------------
// Inverse-map each output fp16 slot to (n', k); n' = 4h+g gate-interleaved.
__global__ void prep_weights(const float* __restrict__ w_ih, const float* __restrict__ w_hh) {
    int gid  = blockIdx.x * 256 + threadIdx.x;   // 0 .. N4*HID-1
    int idx8 = gid & 7;
    int lane = (gid >> 3) & 31;
    int nb   = (gid >> 8) & 7;
    int kc32 = (gid >> 11) & 31;
    int nt   = gid >> 16;
    int c  = lane >> 2;
    int g4 = lane & 3;
    int kk = ((idx8 >> 1) & 1) * 8 + g4 * 2 + (idx8 & 1);
    int k  = kc32 * 32 + (idx8 >> 2) * 16 + kk;
    int np = nt * 64 + nb * 8 + c;
    int h = np >> 2, gate = np & 3;
    int j = (gate << 10) + h;
    float whh = w_hh[(size_t)j * HID + k];
    float wc  = w_ih[(size_t)j * HID + k] + whh;
    g_Whp[gid] = __float2half_rn(whh);
    g_Wcp[gid] = __float2half_rn(wc);
}

__global__ void prep_wout(const float* __restrict__ w_out) {
    int gid  = blockIdx.x * 256 + threadIdx.x;   // 0 .. 65535
    int idx8 = gid & 7;
    int lane = (gid >> 3) & 31;
    int nb   = (gid >> 8) & 7;
    int kc32 = (gid >> 11) & 31;
    int c  = lane >> 2;
    int g4 = lane & 3;
    int kk = ((idx8 >> 1) & 1) * 8 + g4 * 2 + (idx8 & 1);
    int k  = kc32 * 32 + (idx8 >> 2) * 16 + kk;
    int j  = nb * 8 + c;
    g_WoutP[gid] = __float2half_rn(w_out[(size_t)j * HID + k]);
}

__global__ void prep_bias(const float* __restrict__ st, const float* __restrict__ w_ih,
                          const float* __restrict__ b_ih, const float* __restrict__ b_hh) {
    int gw   = (blockIdx.x * blockDim.x + threadIdx.x) >> 5;
    int lane = threadIdx.x & 31;
    for (int np = gw; np < N4; np += 1024) {
        int h = np >> 2, g = np & 3;
        int j = (g << 10) + h;
        const float* wr = w_ih + (size_t)j * HID;
        float s = 0.f;
        #pragma unroll 8
        for (int k = lane; k < HID; k += 32) s += st[k] * wr[k];
        #pragma unroll
        for (int off = 16; off > 0; off >>= 1) s += __shfl_xor_sync(0xffffffffu, s, off);
        if (lane == 0) {
            float bs = b_ih[j] + b_hh[j];
            g_bp[np] = bs;
            g_g0[np] = s + bs;
        }
    }
}

// ---------------- h0 ----------------
__global__ void h0_part(const float* __restrict__ qf, const float* __restrict__ w_in) {
    __shared__ float sw[H0ROWS];
    int b = blockIdx.x, s = blockIdx.y, tid = threadIdx.x;
    if (tid < H0ROWS) sw[tid] = w_in[s * H0ROWS + tid];
    __syncthreads();
    const float4* q = reinterpret_cast<const float4*>(qf)
                    + ((size_t)b * INLEN + s * H0ROWS) * (HID / 4) + tid;
    float4 acc = make_float4(0.f, 0.f, 0.f, 0.f);
    #pragma unroll 16
    for (int i = 0; i < H0ROWS; i++) {
        float4 v = q[(size_t)i * (HID / 4)];
        float w = sw[i];
        acc.x = fmaf(v.x, w, acc.x);
        acc.y = fmaf(v.y, w, acc.y);
        acc.z = fmaf(v.z, w, acc.z);
        acc.w = fmaf(v.w, w, acc.w);
    }
    g_part4[((size_t)s * BSZ + b) * (HID / 4) + tid] = acc;
}

__global__ void h0_comb(const float* __restrict__ b_in) {
    int b = blockIdx.x, tid = threadIdx.x;
    float4 a = make_float4(0.f, 0.f, 0.f, 0.f);
    #pragma unroll
    for (int s = 0; s < H0S; s++) {
        float4 p = g_part4[((size_t)s * BSZ + b) * (HID / 4) + tid];
        a.x += p.x; a.y += p.y; a.z += p.z; a.w += p.w;
    }
    float bb = b_in[0];
    float v[4] = { a.x + bb, a.y + bb, a.z + bb, a.w + bb };
    int mt = b >> 7, row = b & 127;
    #pragma unroll
    for (int i = 0; i < 4; i++)
        g_act0[a_idx(mt, row, tid * 4 + i)] = __float2half_rn(v[i]);
}

// ---------------- GEMM core (fp16 m16n8k16, 4-slot cp.async pipeline) ----------------
extern __shared__ char dynsm[];

__device__ __forceinline__ void stage_cp(const __half* Ablk, const __half* Wblk,
                                         int kt, int tid) {
    char* s = dynsm + (size_t)(kt & 3) * SLOT_BYTES;
    const char* gA = (const char*)(Ablk + (size_t)kt * 8192);   // 128x64 fp16 = 16KB
    const char* gB = (const char*)(Wblk + (size_t)kt * 4096);   // 64x64 fp16 = 8KB
    #pragma unroll
    for (int i = 0; i < 4; i++) { int o = (tid + i * 256) * 16; cp16c(s + o, gA + o); }
    #pragma unroll
    for (int i = 0; i < 2; i++) { int o = (tid + i * 256) * 16; cp16c(s + 16384 + o, gB + o); }
}

__device__ __forceinline__ void run_gemm(const __half* __restrict__ Ablk,
                                         const __half* __restrict__ Wblk,
                                         float (&acc)[2][4][4],
                                         int tid, int lane, int wm, int wn) {
    #pragma unroll
    for (int i = 0; i < 2; i++)
        #pragma unroll
        for (int j = 0; j < 4; j++)
            #pragma unroll
            for (int r = 0; r < 4; r++) acc[i][j][r] = 0.f;

    stage_cp(Ablk, Wblk, 0, tid);
    asm volatile("cp.async.commit_group;\n" ::: "memory");
    stage_cp(Ablk, Wblk, 1, tid);
    asm volatile("cp.async.commit_group;\n" ::: "memory");
    stage_cp(Ablk, Wblk, 2, tid);
    asm volatile("cp.async.commit_group;\n" ::: "memory");

    #pragma unroll 1
    for (int kt = 0; kt < NKT; kt++) {
        if (kt < NKT - 2)       asm volatile("cp.async.wait_group 2;\n" ::: "memory");
        else if (kt == NKT - 2) asm volatile("cp.async.wait_group 1;\n" ::: "memory");
        else                    asm volatile("cp.async.wait_group 0;\n" ::: "memory");
        __syncthreads();
        if (kt + 3 < NKT) {
            stage_cp(Ablk, Wblk, kt + 3, tid);
            asm volatile("cp.async.commit_group;\n" ::: "memory");
        }
        const float4* A4 = reinterpret_cast<const float4*>(dynsm + (size_t)(kt & 3) * SLOT_BYTES);
        const float4* B4 = reinterpret_cast<const float4*>(dynsm + (size_t)(kt & 3) * SLOT_BYTES + 16384);

        float4 af[2][2];      // double-buffered A frags per kc16
        float4 bq[2][4];      // B frags per kc32 pair (x,y = even kc16; z,w = odd)
        #pragma unroll
        for (int mb = 0; mb < 2; mb++) af[0][mb] = A4[(wm * 2 + mb) * 32 + lane];
        #pragma unroll
        for (int nb = 0; nb < 4; nb++) bq[0][nb] = B4[(wn * 4 + nb) * 32 + lane];

        #pragma unroll
        for (int kc = 0; kc < 4; kc++) {
            if (kc == 0) {
                #pragma unroll
                for (int nb = 0; nb < 4; nb++)
                    bq[1][nb] = B4[(8 + wn * 4 + nb) * 32 + lane];
            }
            if (kc < 3) {
                #pragma unroll
                for (int mb = 0; mb < 2; mb++)
                    af[(kc + 1) & 1][mb] = A4[((kc + 1) * 8 + wm * 2 + mb) * 32 + lane];
            }
            #pragma unroll
            for (int mb = 0; mb < 2; mb++)
                #pragma unroll
                for (int nb = 0; nb < 4; nb++) {
                    const float4& b4 = bq[kc >> 1][nb];
                    if (kc & 1) mma_f16(acc[mb][nb], af[kc & 1][mb], b4.z, b4.w);
                    else        mma_f16(acc[mb][nb], af[kc & 1][mb], b4.x, b4.y);
                }
        }
    }
    __syncthreads();   // all slots consumed before smem reuse (C stash)
}

__device__ __forceinline__ void store_C(float (&acc)[2][4][4], int lane, int wm, int wn) {
    float* Cs = reinterpret_cast<float*>(dynsm);
    #pragma unroll
    for (int mb = 0; mb < 2; mb++)
        #pragma unroll
        for (int nb = 0; nb < 4; nb++) {
            int r  = (wm * 2 + mb) * 16 + (lane >> 2);
            int cc = (wn * 4 + nb) * 8 + (lane & 3) * 2;
            Cs[r * CSTRIDE + cc]           = acc[mb][nb][0];
            Cs[r * CSTRIDE + cc + 1]       = acc[mb][nb][1];
            Cs[(r + 8) * CSTRIDE + cc]     = acc[mb][nb][2];
            Cs[(r + 8) * CSTRIDE + cc + 1] = acc[mb][nb][3];
        }
}

// ---------------- persistent LSTM + projection ----------------
__global__ void __launch_bounds__(256, 1)
lstm_persist(const float* __restrict__ b_out, float* __restrict__ probs_dst) {
    const int tid  = threadIdx.x;
    const int lane = tid & 31;
    const int w    = tid >> 5;
    const int wm   = w & 3;
    const int wn   = w >> 2;
    const int mt   = blockIdx.x;     // 0..1
    const int nt   = blockIdx.y;     // 0..63
    const int mBase = mt * BM;

    float acc[2][4][4];
    float c_reg[8];                  // cell state: this CTA owns (mt rows x nt's 16 h-groups)
    #pragma unroll
    for (int i = 0; i < 8; i++) c_reg[i] = 0.f;

    #pragma unroll 1
    for (int t = 0; t < TSTEPS; t++) {
        const __half* A    = ((t & 1) ? g_act1 : g_act0) + (size_t)mt * A_MT_ELEMS;
        __half*       nact = (t & 1) ? g_act0 : g_act1;
        const __half* W    = ((t == 0) ? g_Whp : g_Wcp) + (size_t)nt * B_NT_ELEMS;
        const float*  bias = (t == 0) ? g_g0 : g_bp;

        run_gemm(A, W, acc, tid, lane, wm, wn);
        store_C(acc, lane, wm, wn);
        __syncthreads();

        const float* Cs = reinterpret_cast<const float*>(dynsm);
        #pragma unroll
        for (int i = 0; i < 8; i++) {
            int idx = tid + i * 256;          // 128 rows x 16 h-groups
            int row = idx >> 4, hh = idx & 15;
            int b = mBase + row;
            float4 gv = *reinterpret_cast<const float4*>(&Cs[row * CSTRIDE + hh * 4]);
            float4 bb = *reinterpret_cast<const float4*>(&bias[nt * 64 + hh * 4]);
            float gi = gv.x + bb.x;
            float gf = gv.y + bb.y;
            float gg = gv.z + bb.z;
            float go = gv.w + bb.w;
            float cN = sigm(gf) * c_reg[i] + sigm(gi) * tanh_acc(gg);
            float hN = sigm(go) * tanh_acc(cN);
            c_reg[i] = cN;
            int hg = nt * 16 + hh;
            g_out[((size_t)b * TSTEPS + t) * HID + hg] = hN;
            __half hv = __float2half_rn(hN);
            nact[a_idx(mt, row, hg)] = hv;
            int r2 = b * TSTEPS + t;
            g_A2[a_idx(r2 >> 7, r2 & 127, hg)] = hv;
        }
        grid_bar();
    }

    // projection: A2 [16384 x 1024] @ WoutP^T [64 x 1024] over 128 m-tiles
    if (probs_dst != nullptr) {
        int bid = mt + 2 * nt;               // 0..127
        run_gemm(g_A2 + (size_t)bid * A_MT_ELEMS, g_WoutP, acc, tid, lane, wm, wn);
        store_C(acc, lane, wm, wn);
        __syncthreads();
        const float* Cs = reinterpret_cast<const float*>(dynsm);
        int pBase = bid * BM;
        #pragma unroll 1
        for (int idx = tid; idx < BM * OUTW; idx += 256) {
            int row = idx >> 6, col = idx & 63;
            probs_dst[(size_t)(pBase + row) * OUTW + col] = Cs[row * CSTRIDE + col] + b_out[col];
        }
    }
}

// ---------------- host ----------------
extern "C" void kernel_launch(void* const* d_in, const int* in_sizes, int n_in,
                              void* d_out, int out_size) {
    const float* qf    = (const float*)d_in[1];
    const float* st    = (const float*)d_in[4];
    const float* w_in  = (const float*)d_in[5];
    const float* b_in  = (const float*)d_in[6];
    const float* w_ih  = (const float*)d_in[7];
    const float* w_hh  = (const float*)d_in[8];
    const float* b_ih  = (const float*)d_in[9];
    const float* b_hh  = (const float*)d_in[10];
    const float* w_out = (const float*)d_in[11];
    const float* b_out = (const float*)d_in[12];
    float* out = (float*)d_out;

    float* p_hout;
    cudaGetSymbolAddress((void**)&p_hout, g_out);

    cudaFuncSetAttribute(lstm_persist, cudaFuncAttributeMaxDynamicSharedMemorySize, SMEM_BYTES);

    prep_weights<<<(N4 * HID) / 256, 256>>>(w_ih, w_hh);
    prep_wout<<<(OUTW * HID) / 256, 256>>>(w_out);
    prep_bias<<<128, 256>>>(st, w_ih, b_ih, b_hh);
    h0_part<<<dim3(BSZ, H0S), 256>>>(qf, w_in);
    h0_comb<<<BSZ, 256>>>(b_in);

    // output routing: reference returns (probs, output)
    const long long PROBS_N = (long long)BSZ * TSTEPS * OUTW;
    const long long OUT_N   = (long long)BSZ * TSTEPS * HID;
    float* probs_dst = nullptr;
    bool copy_hidden = false;
    long long hidden_off = 0;
    if ((long long)out_size >= PROBS_N + OUT_N) {
        probs_dst = out;
        copy_hidden = true;
        hidden_off = PROBS_N;
    } else if ((long long)out_size == OUT_N) {
        copy_hidden = true;
    } else {
        probs_dst = out;
    }

    lstm_persist<<<dim3(2, 64), 256, SMEM_BYTES>>>(b_out, probs_dst);

    if (copy_hidden) {
        cudaMemcpyAsync(out + hidden_off, p_hout, OUT_N * sizeof(float),
                        cudaMemcpyDeviceToDevice);
    }
}